// round 4
// baseline (speedup 1.0000x reference)
#include <cuda_runtime.h>
#include <cstdint>

// Problem constants
#define INC   32
#define INN   50000
#define OUTC  32
#define OUTN  8192
#define MAXD  16
#define NBATCH 8
#define NC    (NBATCH * INC)   // 256

// Scratch: transposed embedding table xt[INN][NC] (51.2 MB, L2-resident)
__device__ __align__(16) float g_xt[(size_t)INN * NC];

// ---------------------------------------------------------------------------
// Kernel 1: transpose x[256][50000] -> xt[50000][256], float4 both sides.
// (Unchanged from R3: measured at ~78% of combined HBM roofline.)
// ---------------------------------------------------------------------------
#define TI 128

__global__ __launch_bounds__(256) void transpose_kernel(const float* __restrict__ x) {
    __shared__ float tile[32][129];
    const int i0  = blockIdx.x * TI;
    const int nc0 = blockIdx.y * 32;
    const int tid = threadIdx.x;

    {
        const int iq_low = tid & 7;
        const int nc_l   = ((tid >> 3) & 3) + 4 * (tid >> 5);   // 0..31
        const int nc     = nc0 + nc_l;
        #pragma unroll
        for (int r = 0; r < 4; r++) {
            const int iq = iq_low + 8 * r;        // 0..31
            const int i  = i0 + iq * 4;
            if (i < INN) {                        // INN%4==0 -> full quad ok
                const float4 v = *reinterpret_cast<const float4*>(
                    x + (size_t)nc * INN + i);
                tile[nc_l][iq * 4 + 0] = v.x;
                tile[nc_l][iq * 4 + 1] = v.y;
                tile[nc_l][iq * 4 + 2] = v.z;
                tile[nc_l][iq * 4 + 3] = v.w;
            }
        }
    }
    __syncthreads();
    {
        const int q  = tid & 7;
        const int ib = tid >> 3;                  // 0..31
        #pragma unroll
        for (int r = 0; r < 4; r++) {
            const int il = ib + 32 * r;           // 0..127
            const int i  = i0 + il;
            if (i < INN) {
                float4 v;
                v.x = tile[4 * q + 0][il];
                v.y = tile[4 * q + 1][il];
                v.z = tile[4 * q + 2][il];
                v.w = tile[4 * q + 3][il];
                *reinterpret_cast<float4*>(g_xt + (size_t)i * NC + nc0 + 4 * q) = v;
            }
        }
    }
}

// ---------------------------------------------------------------------------
// Kernel 2 (fused): gather+pool -> smem -> matmul+bias -> y.
// Block = 8 output nodes, 512 threads.
//
// Phase A (gather): thread = (ol = tid>>6 in 0..7, q = tid&63).
//   pooled[ol][4q..4q+3] = sum_d mask * xt[A][.]   (float4, MLP=16)
// Phase B (epilogue): thread = (ol = tid&7, n = (tid>>3)&7, dg = tid>>6).
//   y[n][4dg+j][o_base+ol] = sum_c pooled[ol][n*32+c]*w[c][4dg+j] + bias
//   - pooled row segment cached in 32 regs
//   - weight LDS.128 is warp-broadcast (dg warp-uniform)
//   - y stores: 8 consecutive o per 8 lanes -> full 32B sectors
// ---------------------------------------------------------------------------
#define O_TILE 8

__global__ __launch_bounds__(512) void fused_kernel(
    const int*   __restrict__ A,       // [OUTN][MAXD]
    const float* __restrict__ mask,    // [OUTN][MAXD]
    const float* __restrict__ weight,  // [INC][OUTC]
    const float* __restrict__ bias,    // [OUTC][OUTN]
    float*       __restrict__ y)       // [NBATCH][OUTC][OUTN]
{
    __shared__ float s_p[O_TILE][NC + 1];       // 8 x 257 floats
    __shared__ float s_w[INC * OUTC];           // 4 KB
    __shared__ int   s_idx[O_TILE * MAXD];      // 128
    __shared__ float s_msk[O_TILE * MAXD];      // 128

    const int tid    = threadIdx.x;
    const int o_base = blockIdx.x * O_TILE;

    if (tid < O_TILE * MAXD) {
        s_idx[tid] = A[(size_t)o_base * MAXD + tid];
        s_msk[tid] = mask[(size_t)o_base * MAXD + tid];
    }
    #pragma unroll
    for (int k = tid; k < INC * OUTC; k += 512) s_w[k] = weight[k];
    __syncthreads();

    // ---- Phase A: gather + pool ----
    {
        const int q  = tid & 63;      // feature quad
        const int ol = tid >> 6;      // 0..7
        float4 acc = make_float4(0.f, 0.f, 0.f, 0.f);
        #pragma unroll
        for (int d = 0; d < MAXD; d++) {
            const int   idx = s_idx[ol * MAXD + d];
            const float m   = s_msk[ol * MAXD + d];
            const float4 v  = *reinterpret_cast<const float4*>(
                g_xt + (size_t)idx * NC + q * 4);
            acc.x += m * v.x;
            acc.y += m * v.y;
            acc.z += m * v.z;
            acc.w += m * v.w;
        }
        s_p[ol][q * 4 + 0] = acc.x;
        s_p[ol][q * 4 + 1] = acc.y;
        s_p[ol][q * 4 + 2] = acc.z;
        s_p[ol][q * 4 + 3] = acc.w;
    }
    __syncthreads();

    // ---- Phase B: matmul + bias + store ----
    {
        const int ol = tid & 7;           // o within tile
        const int n  = (tid >> 3) & 7;    // batch
        const int dg = tid >> 6;          // d-quad 0..7
        const int o  = o_base + ol;

        float p[INC];
        #pragma unroll
        for (int c = 0; c < INC; c++) p[c] = s_p[ol][n * INC + c];

        float4 acc = make_float4(0.f, 0.f, 0.f, 0.f);
        #pragma unroll
        for (int c = 0; c < INC; c++) {
            const float4 w = *reinterpret_cast<const float4*>(
                s_w + c * OUTC + dg * 4);   // warp-broadcast
            acc.x += p[c] * w.x;
            acc.y += p[c] * w.y;
            acc.z += p[c] * w.z;
            acc.w += p[c] * w.w;
        }
        const int d0 = dg * 4;
        const size_t nbase = (size_t)n * (OUTC * OUTN);
        y[nbase + (size_t)(d0 + 0) * OUTN + o] =
            acc.x + bias[(size_t)(d0 + 0) * OUTN + o];
        y[nbase + (size_t)(d0 + 1) * OUTN + o] =
            acc.y + bias[(size_t)(d0 + 1) * OUTN + o];
        y[nbase + (size_t)(d0 + 2) * OUTN + o] =
            acc.z + bias[(size_t)(d0 + 2) * OUTN + o];
        y[nbase + (size_t)(d0 + 3) * OUTN + o] =
            acc.w + bias[(size_t)(d0 + 3) * OUTN + o];
    }
}

// ---------------------------------------------------------------------------
// Launch
// ---------------------------------------------------------------------------
extern "C" void kernel_launch(void* const* d_in, const int* in_sizes, int n_in,
                              void* d_out, int out_size) {
    const float* x      = (const float*)d_in[0];
    const int*   A      = (const int*)  d_in[1];
    const float* mask   = (const float*)d_in[2];
    const float* weight = (const float*)d_in[3];
    const float* bias   = (const float*)d_in[4];
    float*       y      = (float*)d_out;

    {
        dim3 grid((INN + TI - 1) / TI, NC / 32);   // 391 x 8
        transpose_kernel<<<grid, 256>>>(x);
    }
    {
        dim3 grid(OUTN / O_TILE);                   // 1024
        fused_kernel<<<grid, 512>>>(A, mask, weight, bias, y);
    }
}

// round 7
// speedup vs baseline: 1.2275x; 1.2275x over previous
#include <cuda_runtime.h>
#include <cuda_fp16.h>
#include <cstdint>

// Problem constants
#define INC   32
#define INN   50000
#define OUTC  32
#define OUTN  8192
#define MAXD  16
#define NBATCH 8
#define NC    (NBATCH * INC)   // 256

// Transposed embedding table in fp16: xt[INN][NC] (25.6 MB, L2-resident)
__device__ __align__(16) __half g_xt[(size_t)INN * NC];
// Pooled intermediate [OUTN][NC] fp32 (8.4 MB)
__device__ __align__(16) float g_pooled[(size_t)OUTN * NC];

// ---------------------------------------------------------------------------
// Kernel 1: transpose x[256][50000] (f32) -> g_xt[50000][256] (f16).
// Tile: 32 nc x 128 i. smem [32][129] f32.
// Load phase: float4 LDG, scalar STS (conflict-free, as R3).
// Store phase: thread = (g = tid&3 -> nc-octet, ib = tid>>2 -> i), packs
// 8 floats -> 8 halves -> one 16B STG. LDS bank = (8g + k + il) mod 32,
// distinct per lane (g 0..3, il 0..7 within warp) -> conflict-free.
// ---------------------------------------------------------------------------
#define TI 128

__global__ __launch_bounds__(256) void transpose_kernel(const float* __restrict__ x) {
    __shared__ float tile[32][129];
    const int i0  = blockIdx.x * TI;
    const int nc0 = blockIdx.y * 32;
    const int tid = threadIdx.x;

    // ---- Load phase (same as R3) ----
    {
        const int iq_low = tid & 7;
        const int nc_l   = ((tid >> 3) & 3) + 4 * (tid >> 5);   // 0..31
        const int nc     = nc0 + nc_l;
        #pragma unroll
        for (int r = 0; r < 4; r++) {
            const int iq = iq_low + 8 * r;        // 0..31
            const int i  = i0 + iq * 4;
            if (i < INN) {                        // INN%4==0 -> full quad ok
                const float4 v = *reinterpret_cast<const float4*>(
                    x + (size_t)nc * INN + i);
                tile[nc_l][iq * 4 + 0] = v.x;
                tile[nc_l][iq * 4 + 1] = v.y;
                tile[nc_l][iq * 4 + 2] = v.z;
                tile[nc_l][iq * 4 + 3] = v.w;
            }
        }
    }
    __syncthreads();

    // ---- Store phase: fp16 pack, 16B per thread ----
    {
        const int g  = tid & 3;                   // nc-octet within tile
        const int ib = tid >> 2;                  // 0..63
        #pragma unroll
        for (int r = 0; r < 2; r++) {
            const int il = ib + 64 * r;           // 0..127
            const int i  = i0 + il;
            if (i < INN) {
                __half2 h[4];
                #pragma unroll
                for (int j = 0; j < 4; j++) {
                    const float f0 = tile[8 * g + 2 * j + 0][il];
                    const float f1 = tile[8 * g + 2 * j + 1][il];
                    h[j] = __floats2half2_rn(f0, f1);
                }
                *reinterpret_cast<uint4*>(
                    g_xt + (size_t)i * NC + nc0 + 8 * g) =
                    *reinterpret_cast<const uint4*>(h);
            }
        }
    }
}

// ---------------------------------------------------------------------------
// Kernel 2: gather + pool (fp16 table, fp32 accumulate).
// One warp = one output node o; lane owns 8 features (16B chunk).
//   pooled[o][nc] = sum_d mask[o][d] * xt[A[o][d]][nc]
// Block: 8 warps = 8 o. Each lane: 16 independent LDG.128 (MLP=16).
// ---------------------------------------------------------------------------
__global__ __launch_bounds__(256) void gather_kernel(
    const int*   __restrict__ A,      // [OUTN][MAXD]
    const float* __restrict__ mask)   // [OUTN][MAXD]
{
    __shared__ int   s_idx[8 * MAXD];
    __shared__ float s_msk[8 * MAXD];

    const int tid    = threadIdx.x;
    const int lane   = tid & 31;      // feature chunk: features [8*lane, 8*lane+7]
    const int ol     = tid >> 5;      // warp = o within tile
    const int o_base = blockIdx.x * 8;

    if (tid < 8 * MAXD) {
        s_idx[tid] = A[(size_t)o_base * MAXD + tid];
        s_msk[tid] = mask[(size_t)o_base * MAXD + tid];
    }
    __syncthreads();

    float2 acc[4];
    #pragma unroll
    for (int j = 0; j < 4; j++) acc[j] = make_float2(0.f, 0.f);

    #pragma unroll
    for (int d = 0; d < MAXD; d++) {
        const int   idx = s_idx[ol * MAXD + d];
        const float m   = s_msk[ol * MAXD + d];
        const uint4 raw = *reinterpret_cast<const uint4*>(
            g_xt + (size_t)idx * NC + lane * 8);
        const __half2* h = reinterpret_cast<const __half2*>(&raw);
        #pragma unroll
        for (int j = 0; j < 4; j++) {
            const float2 f = __half22float2(h[j]);
            acc[j].x += m * f.x;
            acc[j].y += m * f.y;
        }
    }

    float* out = g_pooled + (size_t)(o_base + ol) * NC + lane * 8;
    *reinterpret_cast<float4*>(out + 0) =
        make_float4(acc[0].x, acc[0].y, acc[1].x, acc[1].y);
    *reinterpret_cast<float4*>(out + 4) =
        make_float4(acc[2].x, acc[2].y, acc[3].x, acc[3].y);
}

// ---------------------------------------------------------------------------
// Kernel 3: epilogue matmul + bias (unchanged from R3).
//   y[n][d][o] = sum_c pooled[o][n*32+c] * weight[c][d] + bias[d][o]
// ---------------------------------------------------------------------------
__global__ __launch_bounds__(256) void epilogue_kernel(
    const float* __restrict__ weight,  // [INC][OUTC]
    const float* __restrict__ bias,    // [OUTC][OUTN]
    float*       __restrict__ y)       // [NBATCH][OUTC][OUTN]
{
    __shared__ float s_p[32][257];     // padded: o-column reads conflict-free
    __shared__ float s_w[INC * OUTC];  // 4 KB

    const int tid    = threadIdx.x;
    const int o_base = blockIdx.x * 32;

    #pragma unroll
    for (int k = tid; k < INC * OUTC; k += 256) s_w[k] = weight[k];

    #pragma unroll
    for (int t = tid; t < 32 * 64; t += 256) {
        const int chunk = t >> 8;                 // 0..7
        const int within = t & 255;
        const int row = within >> 3;              // 0..31
        const int qq  = (within & 7) + 8 * chunk; // 0..63
        const float4 v = *reinterpret_cast<const float4*>(
            g_pooled + (size_t)(o_base + row) * NC + qq * 4);
        s_p[row][qq * 4 + 0] = v.x;
        s_p[row][qq * 4 + 1] = v.y;
        s_p[row][qq * 4 + 2] = v.z;
        s_p[row][qq * 4 + 3] = v.w;
    }
    __syncthreads();

    const int o_lane = tid & 31;
    const int n      = tid >> 5;      // 0..7
    const int o      = o_base + o_lane;

    float p[INC];
    #pragma unroll
    for (int c = 0; c < INC; c++) p[c] = s_p[o_lane][n * INC + c];

    #pragma unroll
    for (int dg = 0; dg < 8; dg++) {
        float4 acc = make_float4(0.f, 0.f, 0.f, 0.f);
        #pragma unroll
        for (int c = 0; c < INC; c++) {
            const float4 w = *reinterpret_cast<const float4*>(
                s_w + c * OUTC + dg * 4);   // warp-broadcast
            acc.x += p[c] * w.x;
            acc.y += p[c] * w.y;
            acc.z += p[c] * w.z;
            acc.w += p[c] * w.w;
        }
        const int d0 = dg * 4;
        y[(size_t)n * (OUTC * OUTN) + (size_t)(d0 + 0) * OUTN + o] =
            acc.x + bias[(size_t)(d0 + 0) * OUTN + o];
        y[(size_t)n * (OUTC * OUTN) + (size_t)(d0 + 1) * OUTN + o] =
            acc.y + bias[(size_t)(d0 + 1) * OUTN + o];
        y[(size_t)n * (OUTC * OUTN) + (size_t)(d0 + 2) * OUTN + o] =
            acc.z + bias[(size_t)(d0 + 2) * OUTN + o];
        y[(size_t)n * (OUTC * OUTN) + (size_t)(d0 + 3) * OUTN + o] =
            acc.w + bias[(size_t)(d0 + 3) * OUTN + o];
    }
}

// ---------------------------------------------------------------------------
// Launch
// ---------------------------------------------------------------------------
extern "C" void kernel_launch(void* const* d_in, const int* in_sizes, int n_in,
                              void* d_out, int out_size) {
    const float* x      = (const float*)d_in[0];
    const int*   A      = (const int*)  d_in[1];
    const float* mask   = (const float*)d_in[2];
    const float* weight = (const float*)d_in[3];
    const float* bias   = (const float*)d_in[4];
    float*       y      = (float*)d_out;

    {
        dim3 grid((INN + TI - 1) / TI, NC / 32);   // 391 x 8
        transpose_kernel<<<grid, 256>>>(x);
    }
    {
        dim3 grid(OUTN / 8);                        // 1024
        gather_kernel<<<grid, 256>>>(A, mask);
    }
    {
        dim3 grid(OUTN / 32);                       // 256
        epilogue_kernel<<<grid, 256>>>(weight, bias, y);
    }
}